// round 15
// baseline (speedup 1.0000x reference)
#include <cuda_runtime.h>
#include <cuda_fp16.h>
#include <math.h>
#include <stdint.h>

// ---------------- problem constants (fixed by dataset) ----------------
#define B_     8
#define T2_    27
#define T3_    9
#define P_     17
#define C_     128
#define BT2_   216
#define LQ_    153
#define LV_    4080
#define NH_    8
#define NL_    4
#define NP_    4
#define DH_    16
#define NROWS_ (BT2_*LQ_)     // 33048
#define MVAL_  (BT2_*LV_)     // 881280
#define NEWQ_SIZE_ ((size_t)NROWS_*C_)
#define NOFF_  256
#define NCAT_  384
// chunking: 8 chunks of 27 batches each
#define NCHUNK_ 8
#define CB_ 27
#define CROWS_ (CB_*LV_)      // 110160 value rows per chunk

// ---------------- scratch ----------------
__device__ float g_offatt[(size_t)NROWS_ * NCAT_];
__device__ float g_samp[(size_t)NROWS_ * C_];
__device__ float g_bcat[NCAT_];
// fp16 weight images, XOR-swizzled [n][k] layout with K-PERMUTED columns,
// 5 chunks of 128x128: 0: W_val, 1: W_off lo, 2: W_off hi, 3: W_attn, 4: W_out
__device__ uint32_t g_wb[5 * 8192];   // 32KB per chunk

__device__ __forceinline__ uint32_t smem_u32(const void* p) {
    uint32_t a;
    asm("{ .reg .u64 t; cvta.to.shared.u64 t, %1; cvt.u32.u64 %0, t; }" : "=r"(a) : "l"(p));
    return a;
}

__device__ __forceinline__ uint32_t swz(uint32_t c, uint32_t rm) {
    return (c & 15u) | ((((c >> 4) ^ rm) & 15u) << 4);
}

// ---------------- prep: build 5 fp16 K-permuted weight-chunk images --------
// Fragment slot l (within a 16-col k-block, l = 8h + 2j + b) is fed by A's
// physical column p = 4j + 2h + b (so A fragments load as one float4).
__global__ void prep_images(const float* __restrict__ W_val,
                            const float* __restrict__ W_off,
                            const float* __restrict__ W_attn,
                            const float* __restrict__ W_out)
{
    const float* srcs[5] = {W_val, W_off, W_off + 16384, W_attn, W_out};
    const float* W = srcs[blockIdx.x];
    unsigned short* img = (unsigned short*)(g_wb + blockIdx.x * 8192);
    for (int i = threadIdx.x; i < 16384; i += 256) {
        int n = i >> 7, l = i & 127;
        int lo = l & 15;
        int h = lo >> 3, j = (lo >> 1) & 3, b = lo & 1;
        int srck = (l & ~15) + 4 * j + 2 * h + b;
        __half hv = __float2half_rn(W[n * 128 + srck]);
        uint32_t byte = (uint32_t)n * 256u + swz((uint32_t)l * 2u, (uint32_t)(n & 7));
        img[byte >> 1] = *(unsigned short*)&hv;
    }
}

__global__ void concat_bias(const float* __restrict__ boff, const float* __restrict__ battn) {
    int i = threadIdx.x;
    if (i < NCAT_) g_bcat[i] = (i < NOFF_) ? boff[i] : battn[i - NOFF_];
}

// ---------------- ldmatrix / mma helpers ----------------
#define LDSM4(r0, r1, r2, r3, addr) \
    asm volatile("ldmatrix.sync.aligned.m8n8.x4.shared.b16 {%0,%1,%2,%3}, [%4];" \
                 : "=r"(r0), "=r"(r1), "=r"(r2), "=r"(r3) : "r"(addr))

#define MMAH16816(c, a, b0, b1) \
    asm volatile("mma.sync.aligned.m16n8k16.row.col.f32.f16.f16.f32 " \
                 "{%0,%1,%2,%3},{%4,%5,%6,%7},{%8,%9},{%0,%1,%2,%3};" \
                 : "+f"((c)[0]), "+f"((c)[1]), "+f"((c)[2]), "+f"((c)[3]) \
                 : "r"((a)[0]), "r"((a)[1]), "r"((a)[2]), "r"((a)[3]), "r"(b0), "r"(b1))

// ---------------- unified HMMA fp16 GEMM (K-permuted fragments) ------------
// Out = A * W^T + bias.  Both operands fp16 (rel err ~4.3e-4 total).
// CTA: 128 threads (4 warps), tile 64(M) x 128(N), K = 128, warp 32x64 (2x2).
// A fragments: one LDG.128 per (band, row-half, k-step) thanks to the
// K-permutation baked into the W image. No A smem. Barrier-free mainloop.
#define CTM 64
#define VP_SMEM 32768

__global__ __launch_bounds__(128, 4)
void hmma_gemm(const float* __restrict__ A,
               const uint32_t* __restrict__ wimg_base,
               const float* __restrict__ bias_base,
               float* __restrict__ Out,
               int M, int ldout, int mtiles)
{
    extern __shared__ char sm[];
    const uint32_t sbase = smem_u32(sm);
    const int tid = threadIdx.x;
    const int wid = tid >> 5;
    const int lane = tid & 31;
    const int wm = wid & 1;          // m half (32 rows)
    const int wn = wid >> 1;         // n half (64 cols)
    const int colbase = blockIdx.y * 128;
    const float* bias = bias_base + colbase;

    // copy this chunk's pre-permuted fp16 W image into smem (once)
    {
        const float4* s4 = (const float4*)(wimg_base + blockIdx.y * 8192);
        float4* d4 = (float4*)sm;
#pragma unroll
        for (int i = 0; i < 16; i++) d4[tid + i * 128] = s4[tid + i * 128];
    }
    __syncthreads();   // only barrier in the kernel

    // B fragment addressing (loop-invariant)
    const int sel = lane >> 3;            // 0..3
    const int li  = lane & 7;
    const int bchunkbit = sel & 1;
    const int bro = (sel >> 1) * 8 + li;
    uint32_t bBase[4];
#pragma unroll
    for (int g = 0; g < 4; g++) {
        uint32_t nrow = (uint32_t)(wn * 64 + g * 16 + bro);
        bBase[g] = sbase + nrow * 256u;
    }

    // A fragment addressing: row = lane>>2, float4 col group = lane&3
    const int ar = lane >> 2;             // 0..7
    const int aj = lane & 3;              // float4 group

    for (int tile = blockIdx.x; tile < mtiles; tile += gridDim.x) {
        const int bm = tile * CTM;
        const int r0 = bm + wm * 32 + ar;

        float c[2][8][4];
#pragma unroll
        for (int s = 0; s < 2; s++)
#pragma unroll
            for (int t = 0; t < 8; t++)
#pragma unroll
                for (int j = 0; j < 4; j++) c[s][t][j] = 0.f;

#pragma unroll
        for (int kk = 0; kk < 8; kk++) {
            // A: one float4 per (band, row-half); permutation puts fragment
            // slots {2j,2j+1} in .xy and {8+2j,8+2j+1} in .zw
            uint32_t a[2][4];
#pragma unroll
            for (int s = 0; s < 2; s++) {
                const int r = r0 + s * 16;
                const bool v0 = r < M;
                const bool v1 = (r + 8) < M;
                const float* p0 = A + (size_t)r * 128 + kk * 16 + aj * 4;
                float4 f0 = v0 ? *(const float4*)(p0)           : make_float4(0.f, 0.f, 0.f, 0.f);
                float4 f1 = v1 ? *(const float4*)(p0 + 8 * 128) : make_float4(0.f, 0.f, 0.f, 0.f);
                __half2 q;
                q = __floats2half2_rn(f0.x, f0.y); a[s][0] = *(uint32_t*)&q;
                q = __floats2half2_rn(f1.x, f1.y); a[s][1] = *(uint32_t*)&q;
                q = __floats2half2_rn(f0.z, f0.w); a[s][2] = *(uint32_t*)&q;
                q = __floats2half2_rn(f1.z, f1.w); a[s][3] = *(uint32_t*)&q;
            }

            const uint32_t offB = (uint32_t)(((kk * 2 + bchunkbit) ^ li) << 4);
#pragma unroll
            for (int g = 0; g < 4; g++) {
                uint32_t bh[4];
                LDSM4(bh[0], bh[1], bh[2], bh[3], bBase[g] + offB);
#pragma unroll
                for (int s = 0; s < 2; s++) {
                    MMAH16816(c[s][2 * g],     a[s], bh[0], bh[1]);
                    MMAH16816(c[s][2 * g + 1], a[s], bh[2], bh[3]);
                }
            }
        }

        // epilogue: bias + direct global stores
        {
            const int ncol = wn * 64 + 2 * (lane & 3);
#pragma unroll
            for (int s = 0; s < 2; s++) {
                const int m0 = bm + wm * 32 + s * 16 + (lane >> 2);
                const bool v0 = m0 < M;
                const bool v1 = (m0 + 8) < M;
                float* o0 = Out + (size_t)m0 * ldout + colbase;
                float* o1 = Out + (size_t)(m0 + 8) * ldout + colbase;
#pragma unroll
                for (int t = 0; t < 8; t++) {
                    int n = ncol + t * 8;
                    float2 bb = __ldg((const float2*)(bias + n));
                    if (v0) *(float2*)(o0 + n) = make_float2(c[s][t][0] + bb.x, c[s][t][1] + bb.y);
                    if (v1) *(float2*)(o1 + n) = make_float2(c[s][t][2] + bb.x, c[s][t][3] + bb.y);
                }
            }
        }
    }
}

// ---------------- deformable bilinear gather (softmax fused, chunked) ------
__global__ __launch_bounds__(128) void gather_kernel(
    const float* __restrict__ newv,
    const float* __restrict__ refp,
    int roffs)
{
    int g = blockIdx.x * 4 + (threadIdx.x >> 5);
    int r = roffs + (g >> 3);
    int h = g & 7;
    int lane = threadIdx.x & 31;
    int s = lane >> 1;           // sample 0..15
    int half = lane & 1;
    int l = s >> 2, p = s & 3;
    int b = r / LQ_;

    const int W = 48 >> l;
    const int H = 64 >> l;
    const int start = 4096 - (4096 >> (2 * l));

    int sidx = (h * 4 + l) * 4 + p;
    const float* orow = g_offatt + (size_t)r * NCAT_;
    float offx = orow[sidx * 2 + 0];
    float offy = orow[sidx * 2 + 1];

    // fused softmax over the 16 samples of this (r,h)
    float logit = orow[NOFF_ + h * 16 + s];
    float mx = logit;
#pragma unroll
    for (int m = 2; m <= 16; m <<= 1) mx = fmaxf(mx, __shfl_xor_sync(0xffffffffu, mx, m));
    float e = expf(logit - mx);
    float se = e;
#pragma unroll
    for (int m = 2; m <= 16; m <<= 1) se += __shfl_xor_sync(0xffffffffu, se, m);
    float aw = e / se;

    const float* rp = refp + ((size_t)r * 4 + l) * 2;
    float locx = rp[0] + offx / (float)W;
    float locy = rp[1] + offy / (float)H;
    float px = locx * (float)W - 0.5f;
    float py = locy * (float)H - 0.5f;
    float x0f = floorf(px), y0f = floorf(py);
    float fx = px - x0f, fy = py - y0f;
    int x0 = (int)x0f, y0 = (int)y0f;

    float cw00 = (1.f - fx) * (1.f - fy) * aw;
    float cw10 = fx * (1.f - fy) * aw;
    float cw01 = (1.f - fx) * fy * aw;
    float cw11 = fx * fy * aw;

    const float* base = newv + ((size_t)b * LV_ + start) * C_ + h * DH_ + half * 8;

    float acc[8] = {0.f, 0.f, 0.f, 0.f, 0.f, 0.f, 0.f, 0.f};
    auto corner = [&](int xi, int yi, float cw) {
        if ((unsigned)xi < (unsigned)W && (unsigned)yi < (unsigned)H) {
            const float4* vp = (const float4*)(base + ((size_t)yi * W + xi) * C_);
            float4 v0 = vp[0], v1 = vp[1];
            acc[0] += cw * v0.x; acc[1] += cw * v0.y;
            acc[2] += cw * v0.z; acc[3] += cw * v0.w;
            acc[4] += cw * v1.x; acc[5] += cw * v1.y;
            acc[6] += cw * v1.z; acc[7] += cw * v1.w;
        }
    };
    corner(x0,     y0,     cw00);
    corner(x0 + 1, y0,     cw10);
    corner(x0,     y0 + 1, cw01);
    corner(x0 + 1, y0 + 1, cw11);

#pragma unroll
    for (int m = 2; m <= 16; m <<= 1) {
#pragma unroll
        for (int i = 0; i < 8; i++)
            acc[i] += __shfl_xor_sync(0xffffffffu, acc[i], m);
    }

    if (s == 0) {
        float* dst = g_samp + (size_t)r * C_ + h * DH_ + half * 8;
        *(float4*)(dst + 0) = make_float4(acc[0], acc[1], acc[2], acc[3]);
        *(float4*)(dst + 4) = make_float4(acc[4], acc[5], acc[6], acc[7]);
    }
}

// ---------------- launch ----------------
extern "C" void kernel_launch(void* const* d_in, const int* in_sizes, int n_in,
                              void* d_out, int out_size)
{
    const float* query  = (const float*)d_in[0];
    const float* refp   = (const float*)d_in[1];
    const float* value  = (const float*)d_in[2];
    const float* W_off  = (const float*)d_in[5];
    const float* b_off  = (const float*)d_in[6];
    const float* W_attn = (const float*)d_in[7];
    const float* b_attn = (const float*)d_in[8];
    const float* W_val  = (const float*)d_in[9];
    const float* b_val  = (const float*)d_in[10];
    const float* W_out  = (const float*)d_in[11];
    const float* b_out  = (const float*)d_in[12];

    float* NEWQ = (float*)d_out;
    float* NEWV = NEWQ + NEWQ_SIZE_;

    float *p_offatt, *p_samp, *p_bcat;
    uint32_t *p_wb;
    cudaGetSymbolAddress((void**)&p_offatt, g_offatt);
    cudaGetSymbolAddress((void**)&p_samp,   g_samp);
    cudaGetSymbolAddress((void**)&p_bcat,   g_bcat);
    cudaGetSymbolAddress((void**)&p_wb,     g_wb);

    cudaFuncSetAttribute(hmma_gemm, cudaFuncAttributeMaxDynamicSharedMemorySize, VP_SMEM);

    // 1) prep K-permuted weight images + bias concat
    prep_images<<<5, 256>>>(W_val, W_off, W_attn, W_out);
    concat_bias<<<1, NCAT_>>>(b_off, b_attn);

    // 2) offsets + attn logits (3 weight chunks: indices 1..3)
    {
        int mtiles = (NROWS_ + CTM - 1) / CTM;  // 517
        hmma_gemm<<<dim3(mtiles, 3), 128, VP_SMEM>>>(
            query, p_wb + 8192, p_bcat, p_offatt, NROWS_, NCAT_, mtiles);
    }

    // 3) chunked: vproj chunk -> gather chunk (NEWV slice stays L2-hot)
    {
        int mtiles = CROWS_ / CTM;                  // 1721.25 -> exact: 110160/64
        int gblocks = CB_ * LQ_ * NH_ / 4;          // 8262
        for (int ch = 0; ch < NCHUNK_; ch++) {
            size_t voff = (size_t)ch * CROWS_ * 128;
            hmma_gemm<<<dim3((CROWS_ + CTM - 1) / CTM, 1), 128, VP_SMEM>>>(
                value + voff, p_wb, b_val, NEWV + voff, CROWS_, 128, (CROWS_ + CTM - 1) / CTM);
            gather_kernel<<<gblocks, 128>>>(NEWV, refp, ch * CB_ * LQ_);
        }
        (void)mtiles;
    }

    // 4) output projection -> new_query (chunk 4)
    {
        int mtiles = (NROWS_ + CTM - 1) / CTM;
        hmma_gemm<<<dim3(mtiles, 1), 128, VP_SMEM>>>(
            p_samp, p_wb + 4 * 8192, b_out, NEWQ, NROWS_, 128, mtiles);
    }
}

// round 16
// speedup vs baseline: 1.0025x; 1.0025x over previous
#include <cuda_runtime.h>
#include <cuda_fp16.h>
#include <math.h>
#include <stdint.h>

// ---------------- problem constants (fixed by dataset) ----------------
#define B_     8
#define T2_    27
#define T3_    9
#define P_     17
#define C_     128
#define BT2_   216
#define LQ_    153
#define LV_    4080
#define NH_    8
#define NL_    4
#define NP_    4
#define DH_    16
#define NROWS_ (BT2_*LQ_)     // 33048
#define MVAL_  (BT2_*LV_)     // 881280
#define NEWQ_SIZE_ ((size_t)NROWS_*C_)
#define NOFF_  256
#define NCAT_  384

// ---------------- scratch ----------------
__device__ float g_offatt[(size_t)NROWS_ * NCAT_];
__device__ float g_samp[(size_t)NROWS_ * C_];
__device__ float g_bcat[NCAT_];
// fp16 weight images, XOR-swizzled [n][k] layout with K-PERMUTED columns,
// 5 chunks of 128x128: 0: W_val, 1: W_off lo, 2: W_off hi, 3: W_attn, 4: W_out
__device__ uint32_t g_wb[5 * 8192];   // 32KB per chunk

__device__ __forceinline__ uint32_t smem_u32(const void* p) {
    uint32_t a;
    asm("{ .reg .u64 t; cvta.to.shared.u64 t, %1; cvt.u32.u64 %0, t; }" : "=r"(a) : "l"(p));
    return a;
}

__device__ __forceinline__ uint32_t swz(uint32_t c, uint32_t rm) {
    return (c & 15u) | ((((c >> 4) ^ rm) & 15u) << 4);
}

// ---------------- f32x2 packed helpers ----------------
__device__ __forceinline__ unsigned long long dup2(float x) {
    unsigned long long r;
    asm("mov.b64 %0, {%1, %1};" : "=l"(r) : "f"(x));
    return r;
}
__device__ __forceinline__ void ffma2(unsigned long long& d, unsigned long long a, unsigned long long b) {
    asm("fma.rn.f32x2 %0, %1, %2, %0;" : "+l"(d) : "l"(a), "l"(b));
}
__device__ __forceinline__ float2 unpk2(unsigned long long v) {
    float2 f;
    asm("mov.b64 {%0, %1}, %2;" : "=f"(f.x), "=f"(f.y) : "l"(v));
    return f;
}

// ---------------- prep: build 5 fp16 K-permuted weight-chunk images --------
// Fragment slot l (within a 16-col k-block, l = 8h + 2j + b) is fed by A's
// physical column p = 4j + 2h + b (so A fragments load as one float4).
__global__ void prep_images(const float* __restrict__ W_val,
                            const float* __restrict__ W_off,
                            const float* __restrict__ W_attn,
                            const float* __restrict__ W_out)
{
    const float* srcs[5] = {W_val, W_off, W_off + 16384, W_attn, W_out};
    const float* W = srcs[blockIdx.x];
    unsigned short* img = (unsigned short*)(g_wb + blockIdx.x * 8192);
    for (int i = threadIdx.x; i < 16384; i += 256) {
        int n = i >> 7, l = i & 127;
        int lo = l & 15;
        int h = lo >> 3, j = (lo >> 1) & 3, b = lo & 1;
        int srck = (l & ~15) + 4 * j + 2 * h + b;
        __half hv = __float2half_rn(W[n * 128 + srck]);
        uint32_t byte = (uint32_t)n * 256u + swz((uint32_t)l * 2u, (uint32_t)(n & 7));
        img[byte >> 1] = *(unsigned short*)&hv;
    }
}

__global__ void concat_bias(const float* __restrict__ boff, const float* __restrict__ battn) {
    int i = threadIdx.x;
    if (i < NCAT_) g_bcat[i] = (i < NOFF_) ? boff[i] : battn[i - NOFF_];
}

// ---------------- ldmatrix / mma helpers ----------------
#define LDSM4(r0, r1, r2, r3, addr) \
    asm volatile("ldmatrix.sync.aligned.m8n8.x4.shared.b16 {%0,%1,%2,%3}, [%4];" \
                 : "=r"(r0), "=r"(r1), "=r"(r2), "=r"(r3) : "r"(addr))

#define MMAH16816(c, a, b0, b1) \
    asm volatile("mma.sync.aligned.m16n8k16.row.col.f32.f16.f16.f32 " \
                 "{%0,%1,%2,%3},{%4,%5,%6,%7},{%8,%9},{%0,%1,%2,%3};" \
                 : "+f"((c)[0]), "+f"((c)[1]), "+f"((c)[2]), "+f"((c)[3]) \
                 : "r"((a)[0]), "r"((a)[1]), "r"((a)[2]), "r"((a)[3]), "r"(b0), "r"(b1))

// ---------------- unified HMMA fp16 GEMM (K-permuted fragments) ------------
// Out = A * W^T + bias.  Both operands fp16 (rel err ~4.3e-4 total).
// CTA: 128 threads (4 warps), tile 64(M) x 128(N), K = 128, warp 32x64 (2x2).
// A fragments: one LDG.128 per (band, row-half, k-step) thanks to the
// K-permutation baked into the W image. No A smem. Barrier-free mainloop.
#define CTM 64
#define VP_SMEM 32768

__global__ __launch_bounds__(128, 4)
void hmma_gemm(const float* __restrict__ A,
               const uint32_t* __restrict__ wimg_base,
               const float* __restrict__ bias_base,
               float* __restrict__ Out,
               int M, int ldout, int mtiles)
{
    extern __shared__ char sm[];
    const uint32_t sbase = smem_u32(sm);
    const int tid = threadIdx.x;
    const int wid = tid >> 5;
    const int lane = tid & 31;
    const int wm = wid & 1;          // m half (32 rows)
    const int wn = wid >> 1;         // n half (64 cols)
    const int colbase = blockIdx.y * 128;
    const float* bias = bias_base + colbase;

    // copy this chunk's pre-permuted fp16 W image into smem (once)
    {
        const float4* s4 = (const float4*)(wimg_base + blockIdx.y * 8192);
        float4* d4 = (float4*)sm;
#pragma unroll
        for (int i = 0; i < 16; i++) d4[tid + i * 128] = s4[tid + i * 128];
    }
    __syncthreads();   // only barrier in the kernel

    // B fragment addressing (loop-invariant)
    const int sel = lane >> 3;            // 0..3
    const int li  = lane & 7;
    const int bchunkbit = sel & 1;
    const int bro = (sel >> 1) * 8 + li;
    uint32_t bBase[4];
#pragma unroll
    for (int g = 0; g < 4; g++) {
        uint32_t nrow = (uint32_t)(wn * 64 + g * 16 + bro);
        bBase[g] = sbase + nrow * 256u;
    }

    // A fragment addressing: row = lane>>2, float4 col group = lane&3
    const int ar = lane >> 2;             // 0..7
    const int aj = lane & 3;              // float4 group

    for (int tile = blockIdx.x; tile < mtiles; tile += gridDim.x) {
        const int bm = tile * CTM;
        const int r0 = bm + wm * 32 + ar;

        float c[2][8][4];
#pragma unroll
        for (int s = 0; s < 2; s++)
#pragma unroll
            for (int t = 0; t < 8; t++)
#pragma unroll
                for (int j = 0; j < 4; j++) c[s][t][j] = 0.f;

#pragma unroll
        for (int kk = 0; kk < 8; kk++) {
            // A: one float4 per (band, row-half); permutation puts fragment
            // slots {2j,2j+1} in .xy and {8+2j,8+2j+1} in .zw
            uint32_t a[2][4];
#pragma unroll
            for (int s = 0; s < 2; s++) {
                const int r = r0 + s * 16;
                const bool v0 = r < M;
                const bool v1 = (r + 8) < M;
                const float* p0 = A + (size_t)r * 128 + kk * 16 + aj * 4;
                float4 f0 = v0 ? *(const float4*)(p0)           : make_float4(0.f, 0.f, 0.f, 0.f);
                float4 f1 = v1 ? *(const float4*)(p0 + 8 * 128) : make_float4(0.f, 0.f, 0.f, 0.f);
                __half2 q;
                q = __floats2half2_rn(f0.x, f0.y); a[s][0] = *(uint32_t*)&q;
                q = __floats2half2_rn(f1.x, f1.y); a[s][1] = *(uint32_t*)&q;
                q = __floats2half2_rn(f0.z, f0.w); a[s][2] = *(uint32_t*)&q;
                q = __floats2half2_rn(f1.z, f1.w); a[s][3] = *(uint32_t*)&q;
            }

            const uint32_t offB = (uint32_t)(((kk * 2 + bchunkbit) ^ li) << 4);
#pragma unroll
            for (int g = 0; g < 4; g++) {
                uint32_t bh[4];
                LDSM4(bh[0], bh[1], bh[2], bh[3], bBase[g] + offB);
#pragma unroll
                for (int s = 0; s < 2; s++) {
                    MMAH16816(c[s][2 * g],     a[s], bh[0], bh[1]);
                    MMAH16816(c[s][2 * g + 1], a[s], bh[2], bh[3]);
                }
            }
        }

        // epilogue: bias + direct global stores
        {
            const int ncol = wn * 64 + 2 * (lane & 3);
#pragma unroll
            for (int s = 0; s < 2; s++) {
                const int m0 = bm + wm * 32 + s * 16 + (lane >> 2);
                const bool v0 = m0 < M;
                const bool v1 = (m0 + 8) < M;
                float* o0 = Out + (size_t)m0 * ldout + colbase;
                float* o1 = Out + (size_t)(m0 + 8) * ldout + colbase;
#pragma unroll
                for (int t = 0; t < 8; t++) {
                    int n = ncol + t * 8;
                    float2 bb = __ldg((const float2*)(bias + n));
                    if (v0) *(float2*)(o0 + n) = make_float2(c[s][t][0] + bb.x, c[s][t][1] + bb.y);
                    if (v1) *(float2*)(o1 + n) = make_float2(c[s][t][2] + bb.x, c[s][t][3] + bb.y);
                }
            }
        }
    }
}

// ---------------- deformable bilinear gather (lean, packed-f32x2) ----------
struct ull2 { unsigned long long x, y; };

__global__ __launch_bounds__(128) void gather_kernel(
    const float* __restrict__ newv,
    const float* __restrict__ refp)
{
    int g = blockIdx.x * 4 + (threadIdx.x >> 5);
    int r = g >> 3;
    int h = g & 7;
    int lane = threadIdx.x & 31;
    int s = lane >> 1;           // sample 0..15
    int half = lane & 1;
    int l = s >> 2, p = s & 3;
    int b = r / LQ_;

    const int W = 48 >> l;
    const int H = 64 >> l;
    const int start = 4096 - (4096 >> (2 * l));

    int sidx = (h * 4 + l) * 4 + p;
    const float* orow = g_offatt + (size_t)r * NCAT_;
    float offx = orow[sidx * 2 + 0];
    float offy = orow[sidx * 2 + 1];

    // softmax over the 16 samples (no max-subtraction: logits are O(1))
    float e = __expf(orow[NOFF_ + h * 16 + s]);
    float se = e;
#pragma unroll
    for (int m = 2; m <= 16; m <<= 1) se += __shfl_xor_sync(0xffffffffu, se, m);
    float aw = e / se;

    const float* rp = refp + ((size_t)r * 4 + l) * 2;
    float px = (rp[0] + offx / (float)W) * (float)W - 0.5f;
    float py = (rp[1] + offy / (float)H) * (float)H - 0.5f;
    float x0f = floorf(px), y0f = floorf(py);
    float fx = px - x0f, fy = py - y0f;
    int x0 = (int)x0f, y0 = (int)y0f;

    float cw00 = (1.f - fx) * (1.f - fy) * aw;
    float cw10 = fx * (1.f - fy) * aw;
    float cw01 = (1.f - fx) * fy * aw;
    float cw11 = fx * fy * aw;

    const char* base = (const char*)(newv + ((size_t)b * LV_ + start) * C_ + h * DH_ + half * 8);

    // batched predicates + addresses, then all 8 loads, then packed FMAs
    const bool m00 = (unsigned)x0 < (unsigned)W       && (unsigned)y0 < (unsigned)H;
    const bool m10 = (unsigned)(x0 + 1) < (unsigned)W && (unsigned)y0 < (unsigned)H;
    const bool m01 = (unsigned)x0 < (unsigned)W       && (unsigned)(y0 + 1) < (unsigned)H;
    const bool m11 = (unsigned)(x0 + 1) < (unsigned)W && (unsigned)(y0 + 1) < (unsigned)H;
    const size_t rowb = (size_t)W * 512;       // bytes per y step
    const char* p00 = base + (size_t)y0 * rowb + (size_t)x0 * 512;
    const char* p10 = p00 + 512;
    const char* p01 = p00 + rowb;
    const char* p11 = p01 + 512;

    ull2 z; z.x = 0ull; z.y = 0ull;
    ull2 a0 = m00 ? *(const ull2*)(p00)      : z;
    ull2 a1 = m00 ? *(const ull2*)(p00 + 16) : z;
    ull2 b0 = m10 ? *(const ull2*)(p10)      : z;
    ull2 b1 = m10 ? *(const ull2*)(p10 + 16) : z;
    ull2 c0 = m01 ? *(const ull2*)(p01)      : z;
    ull2 c1 = m01 ? *(const ull2*)(p01 + 16) : z;
    ull2 d0 = m11 ? *(const ull2*)(p11)      : z;
    ull2 d1 = m11 ? *(const ull2*)(p11 + 16) : z;

    unsigned long long acc2[4] = {0ull, 0ull, 0ull, 0ull};
    {
        unsigned long long w;
        w = dup2(cw00);
        ffma2(acc2[0], w, a0.x); ffma2(acc2[1], w, a0.y);
        ffma2(acc2[2], w, a1.x); ffma2(acc2[3], w, a1.y);
        w = dup2(cw10);
        ffma2(acc2[0], w, b0.x); ffma2(acc2[1], w, b0.y);
        ffma2(acc2[2], w, b1.x); ffma2(acc2[3], w, b1.y);
        w = dup2(cw01);
        ffma2(acc2[0], w, c0.x); ffma2(acc2[1], w, c0.y);
        ffma2(acc2[2], w, c1.x); ffma2(acc2[3], w, c1.y);
        w = dup2(cw11);
        ffma2(acc2[0], w, d0.x); ffma2(acc2[1], w, d0.y);
        ffma2(acc2[2], w, d1.x); ffma2(acc2[3], w, d1.y);
    }

    float acc[8];
    {
        float2 f;
        f = unpk2(acc2[0]); acc[0] = f.x; acc[1] = f.y;
        f = unpk2(acc2[1]); acc[2] = f.x; acc[3] = f.y;
        f = unpk2(acc2[2]); acc[4] = f.x; acc[5] = f.y;
        f = unpk2(acc2[3]); acc[6] = f.x; acc[7] = f.y;
    }

    // reduce over the 16 samples (lane bits 1..4), keep channel-half (bit 0)
#pragma unroll
    for (int m = 2; m <= 16; m <<= 1) {
#pragma unroll
        for (int i = 0; i < 8; i++)
            acc[i] += __shfl_xor_sync(0xffffffffu, acc[i], m);
    }

    if (s == 0) {
        float* dst = g_samp + (size_t)r * C_ + h * DH_ + half * 8;
        *(float4*)(dst + 0) = make_float4(acc[0], acc[1], acc[2], acc[3]);
        *(float4*)(dst + 4) = make_float4(acc[4], acc[5], acc[6], acc[7]);
    }
}

// ---------------- launch ----------------
extern "C" void kernel_launch(void* const* d_in, const int* in_sizes, int n_in,
                              void* d_out, int out_size)
{
    const float* query  = (const float*)d_in[0];
    const float* refp   = (const float*)d_in[1];
    const float* value  = (const float*)d_in[2];
    const float* W_off  = (const float*)d_in[5];
    const float* b_off  = (const float*)d_in[6];
    const float* W_attn = (const float*)d_in[7];
    const float* b_attn = (const float*)d_in[8];
    const float* W_val  = (const float*)d_in[9];
    const float* b_val  = (const float*)d_in[10];
    const float* W_out  = (const float*)d_in[11];
    const float* b_out  = (const float*)d_in[12];

    float* NEWQ = (float*)d_out;
    float* NEWV = NEWQ + NEWQ_SIZE_;

    float *p_offatt, *p_samp, *p_bcat;
    uint32_t *p_wb;
    cudaGetSymbolAddress((void**)&p_offatt, g_offatt);
    cudaGetSymbolAddress((void**)&p_samp,   g_samp);
    cudaGetSymbolAddress((void**)&p_bcat,   g_bcat);
    cudaGetSymbolAddress((void**)&p_wb,     g_wb);

    cudaFuncSetAttribute(hmma_gemm, cudaFuncAttributeMaxDynamicSharedMemorySize, VP_SMEM);

    // 1) prep K-permuted weight images + bias concat
    prep_images<<<5, 256>>>(W_val, W_off, W_attn, W_out);
    concat_bias<<<1, NCAT_>>>(b_off, b_attn);

    // 2) value projection -> new_value (persistent: 4 CTAs/SM x 148 SMs)
    {
        int mtiles = MVAL_ / CTM;               // 13770
        hmma_gemm<<<dim3(592, 1), 128, VP_SMEM>>>(
            value, p_wb, b_val, NEWV, MVAL_, 128, mtiles);
    }

    // 3) offsets + attn logits (3 weight chunks: indices 1..3)
    {
        int mtiles = (NROWS_ + CTM - 1) / CTM;  // 517
        hmma_gemm<<<dim3(mtiles, 3), 128, VP_SMEM>>>(
            query, p_wb + 8192, p_bcat, p_offatt, NROWS_, NCAT_, mtiles);
    }

    // 4) bilinear gather + fused softmax
    gather_kernel<<<NROWS_ * NH_ / 4, 128>>>(NEWV, refp);

    // 5) output projection -> new_query (chunk 4)
    {
        int mtiles = (NROWS_ + CTM - 1) / CTM;
        hmma_gemm<<<dim3(mtiles, 1), 128, VP_SMEM>>>(
            p_samp, p_wb + 4 * 8192, b_out, NEWQ, NROWS_, 128, mtiles);
    }
}

// round 17
// speedup vs baseline: 1.1470x; 1.1442x over previous
#include <cuda_runtime.h>
#include <cuda_fp16.h>
#include <math.h>
#include <stdint.h>

// ---------------- problem constants (fixed by dataset) ----------------
#define B_     8
#define T2_    27
#define T3_    9
#define P_     17
#define C_     128
#define BT2_   216
#define LQ_    153
#define LV_    4080
#define NH_    8
#define NL_    4
#define NP_    4
#define DH_    16
#define NROWS_ (BT2_*LQ_)     // 33048
#define MVAL_  (BT2_*LV_)     // 881280
#define NEWQ_SIZE_ ((size_t)NROWS_*C_)
#define NOFF_  256
#define NCAT_  384

// ---------------- scratch ----------------
__device__ float g_offatt[(size_t)NROWS_ * NCAT_];
__device__ float g_samp[(size_t)NROWS_ * C_];
__device__ float g_bcat[NCAT_];
// fp16 weight images, XOR-swizzled [n][k] layout with K-PERMUTED columns,
// 5 chunks of 128x128: 0: W_val, 1: W_off lo, 2: W_off hi, 3: W_attn, 4: W_out
__device__ uint32_t g_wb[5 * 8192];   // 32KB per chunk

__device__ __forceinline__ uint32_t smem_u32(const void* p) {
    uint32_t a;
    asm("{ .reg .u64 t; cvta.to.shared.u64 t, %1; cvt.u32.u64 %0, t; }" : "=r"(a) : "l"(p));
    return a;
}

__device__ __forceinline__ uint32_t swz(uint32_t c, uint32_t rm) {
    return (c & 15u) | ((((c >> 4) ^ rm) & 15u) << 4);
}

// ---------------- prep: build 5 fp16 K-permuted weight-chunk images --------
// Fragment slot l (within a 16-col k-block, l = 8h + 2j + b) is fed by A's
// physical column p = 4j + 2h + b (so A fragments load as one float4).
__global__ void prep_images(const float* __restrict__ W_val,
                            const float* __restrict__ W_off,
                            const float* __restrict__ W_attn,
                            const float* __restrict__ W_out)
{
    const float* srcs[5] = {W_val, W_off, W_off + 16384, W_attn, W_out};
    const float* W = srcs[blockIdx.x];
    unsigned short* img = (unsigned short*)(g_wb + blockIdx.x * 8192);
    for (int i = threadIdx.x; i < 16384; i += 256) {
        int n = i >> 7, l = i & 127;
        int lo = l & 15;
        int h = lo >> 3, j = (lo >> 1) & 3, b = lo & 1;
        int srck = (l & ~15) + 4 * j + 2 * h + b;
        __half hv = __float2half_rn(W[n * 128 + srck]);
        uint32_t byte = (uint32_t)n * 256u + swz((uint32_t)l * 2u, (uint32_t)(n & 7));
        img[byte >> 1] = *(unsigned short*)&hv;
    }
}

__global__ void concat_bias(const float* __restrict__ boff, const float* __restrict__ battn) {
    int i = threadIdx.x;
    if (i < NCAT_) g_bcat[i] = (i < NOFF_) ? boff[i] : battn[i - NOFF_];
}

// ---------------- ldmatrix / mma helpers ----------------
#define LDSM4(r0, r1, r2, r3, addr) \
    asm volatile("ldmatrix.sync.aligned.m8n8.x4.shared.b16 {%0,%1,%2,%3}, [%4];" \
                 : "=r"(r0), "=r"(r1), "=r"(r2), "=r"(r3) : "r"(addr))

#define MMAH16816(c, a, b0, b1) \
    asm volatile("mma.sync.aligned.m16n8k16.row.col.f32.f16.f16.f32 " \
                 "{%0,%1,%2,%3},{%4,%5,%6,%7},{%8,%9},{%0,%1,%2,%3};" \
                 : "+f"((c)[0]), "+f"((c)[1]), "+f"((c)[2]), "+f"((c)[3]) \
                 : "r"((a)[0]), "r"((a)[1]), "r"((a)[2]), "r"((a)[3]), "r"(b0), "r"(b1))

// ---------------- unified HMMA fp16 GEMM (K-permuted fragments) ------------
// Out = A * W^T + bias.  Both operands fp16 (rel err ~4.3e-4 total).
// CTA: 128 threads (4 warps), tile 64(M) x 128(N), K = 128, warp 32x64 (2x2).
// A fragments: one LDG.128 per (band, row-half, k-step) thanks to the
// K-permutation baked into the W image. No A smem. Barrier-free mainloop.
#define CTM 64
#define VP_SMEM 32768

__global__ __launch_bounds__(128, 4)
void hmma_gemm(const float* __restrict__ A,
               const uint32_t* __restrict__ wimg_base,
               const float* __restrict__ bias_base,
               float* __restrict__ Out,
               int M, int ldout, int mtiles)
{
    extern __shared__ char sm[];
    const uint32_t sbase = smem_u32(sm);
    const int tid = threadIdx.x;
    const int wid = tid >> 5;
    const int lane = tid & 31;
    const int wm = wid & 1;          // m half (32 rows)
    const int wn = wid >> 1;         // n half (64 cols)
    const int colbase = blockIdx.y * 128;
    const float* bias = bias_base + colbase;

    // copy this chunk's pre-permuted fp16 W image into smem (once)
    {
        const float4* s4 = (const float4*)(wimg_base + blockIdx.y * 8192);
        float4* d4 = (float4*)sm;
#pragma unroll
        for (int i = 0; i < 16; i++) d4[tid + i * 128] = s4[tid + i * 128];
    }
    __syncthreads();   // only barrier in the kernel

    // B fragment addressing (loop-invariant)
    const int sel = lane >> 3;            // 0..3
    const int li  = lane & 7;
    const int bchunkbit = sel & 1;
    const int bro = (sel >> 1) * 8 + li;
    uint32_t bBase[4];
#pragma unroll
    for (int g = 0; g < 4; g++) {
        uint32_t nrow = (uint32_t)(wn * 64 + g * 16 + bro);
        bBase[g] = sbase + nrow * 256u;
    }

    // A fragment addressing: row = lane>>2, float4 col group = lane&3
    const int ar = lane >> 2;             // 0..7
    const int aj = lane & 3;              // float4 group

    for (int tile = blockIdx.x; tile < mtiles; tile += gridDim.x) {
        const int bm = tile * CTM;
        const int r0 = bm + wm * 32 + ar;

        float c[2][8][4];
#pragma unroll
        for (int s = 0; s < 2; s++)
#pragma unroll
            for (int t = 0; t < 8; t++)
#pragma unroll
                for (int j = 0; j < 4; j++) c[s][t][j] = 0.f;

#pragma unroll
        for (int kk = 0; kk < 8; kk++) {
            // A: one float4 per (band, row-half); permutation puts fragment
            // slots {2j,2j+1} in .xy and {8+2j,8+2j+1} in .zw
            uint32_t a[2][4];
#pragma unroll
            for (int s = 0; s < 2; s++) {
                const int r = r0 + s * 16;
                const bool v0 = r < M;
                const bool v1 = (r + 8) < M;
                const float* p0 = A + (size_t)r * 128 + kk * 16 + aj * 4;
                float4 f0 = v0 ? *(const float4*)(p0)           : make_float4(0.f, 0.f, 0.f, 0.f);
                float4 f1 = v1 ? *(const float4*)(p0 + 8 * 128) : make_float4(0.f, 0.f, 0.f, 0.f);
                __half2 q;
                q = __floats2half2_rn(f0.x, f0.y); a[s][0] = *(uint32_t*)&q;
                q = __floats2half2_rn(f1.x, f1.y); a[s][1] = *(uint32_t*)&q;
                q = __floats2half2_rn(f0.z, f0.w); a[s][2] = *(uint32_t*)&q;
                q = __floats2half2_rn(f1.z, f1.w); a[s][3] = *(uint32_t*)&q;
            }

            const uint32_t offB = (uint32_t)(((kk * 2 + bchunkbit) ^ li) << 4);
#pragma unroll
            for (int g = 0; g < 4; g++) {
                uint32_t bh[4];
                LDSM4(bh[0], bh[1], bh[2], bh[3], bBase[g] + offB);
#pragma unroll
                for (int s = 0; s < 2; s++) {
                    MMAH16816(c[s][2 * g],     a[s], bh[0], bh[1]);
                    MMAH16816(c[s][2 * g + 1], a[s], bh[2], bh[3]);
                }
            }
        }

        // epilogue: bias + direct global stores
        {
            const int ncol = wn * 64 + 2 * (lane & 3);
#pragma unroll
            for (int s = 0; s < 2; s++) {
                const int m0 = bm + wm * 32 + s * 16 + (lane >> 2);
                const bool v0 = m0 < M;
                const bool v1 = (m0 + 8) < M;
                float* o0 = Out + (size_t)m0 * ldout + colbase;
                float* o1 = Out + (size_t)(m0 + 8) * ldout + colbase;
#pragma unroll
                for (int t = 0; t < 8; t++) {
                    int n = ncol + t * 8;
                    float2 bb = __ldg((const float2*)(bias + n));
                    if (v0) *(float2*)(o0 + n) = make_float2(c[s][t][0] + bb.x, c[s][t][1] + bb.y);
                    if (v1) *(float2*)(o1 + n) = make_float2(c[s][t][2] + bb.x, c[s][t][3] + bb.y);
                }
            }
        }
    }
}

// ---------------- deformable bilinear gather (R13 structure, fast softmax) -
__global__ __launch_bounds__(256) void gather_kernel(
    const float* __restrict__ newv,
    const float* __restrict__ refp)
{
    int g = blockIdx.x * 8 + (threadIdx.x >> 5);
    int r = g >> 3;
    int h = g & 7;
    int lane = threadIdx.x & 31;
    int s = lane >> 1;           // sample 0..15
    int half = lane & 1;
    int l = s >> 2, p = s & 3;
    int b = r / LQ_;

    const int W = 48 >> l;
    const int H = 64 >> l;
    const int start = 4096 - (4096 >> (2 * l));

    int sidx = (h * 4 + l) * 4 + p;
    const float* orow = g_offatt + (size_t)r * NCAT_;
    float offx = orow[sidx * 2 + 0];
    float offy = orow[sidx * 2 + 1];

    // softmax over the 16 samples (no max-subtraction: logits are O(1))
    float e = __expf(orow[NOFF_ + h * 16 + s]);
    float se = e;
#pragma unroll
    for (int m = 2; m <= 16; m <<= 1) se += __shfl_xor_sync(0xffffffffu, se, m);
    float aw = e / se;

    const float* rp = refp + ((size_t)r * 4 + l) * 2;
    float locx = rp[0] + offx / (float)W;
    float locy = rp[1] + offy / (float)H;
    float px = locx * (float)W - 0.5f;
    float py = locy * (float)H - 0.5f;
    float x0f = floorf(px), y0f = floorf(py);
    float fx = px - x0f, fy = py - y0f;
    int x0 = (int)x0f, y0 = (int)y0f;

    float cw00 = (1.f - fx) * (1.f - fy) * aw;
    float cw10 = fx * (1.f - fy) * aw;
    float cw01 = (1.f - fx) * fy * aw;
    float cw11 = fx * fy * aw;

    const float* base = newv + ((size_t)b * LV_ + start) * C_ + h * DH_ + half * 8;

    float acc[8] = {0.f, 0.f, 0.f, 0.f, 0.f, 0.f, 0.f, 0.f};
    auto corner = [&](int xi, int yi, float cw) {
        if ((unsigned)xi < (unsigned)W && (unsigned)yi < (unsigned)H) {
            const float4* vp = (const float4*)(base + ((size_t)yi * W + xi) * C_);
            float4 v0 = vp[0], v1 = vp[1];
            acc[0] += cw * v0.x; acc[1] += cw * v0.y;
            acc[2] += cw * v0.z; acc[3] += cw * v0.w;
            acc[4] += cw * v1.x; acc[5] += cw * v1.y;
            acc[6] += cw * v1.z; acc[7] += cw * v1.w;
        }
    };
    corner(x0,     y0,     cw00);
    corner(x0 + 1, y0,     cw10);
    corner(x0,     y0 + 1, cw01);
    corner(x0 + 1, y0 + 1, cw11);

#pragma unroll
    for (int m = 2; m <= 16; m <<= 1) {
#pragma unroll
        for (int i = 0; i < 8; i++)
            acc[i] += __shfl_xor_sync(0xffffffffu, acc[i], m);
    }

    if (s == 0) {
        float* dst = g_samp + (size_t)r * C_ + h * DH_ + half * 8;
        *(float4*)(dst + 0) = make_float4(acc[0], acc[1], acc[2], acc[3]);
        *(float4*)(dst + 4) = make_float4(acc[4], acc[5], acc[6], acc[7]);
    }
}

// ---------------- launch ----------------
extern "C" void kernel_launch(void* const* d_in, const int* in_sizes, int n_in,
                              void* d_out, int out_size)
{
    const float* query  = (const float*)d_in[0];
    const float* refp   = (const float*)d_in[1];
    const float* value  = (const float*)d_in[2];
    const float* W_off  = (const float*)d_in[5];
    const float* b_off  = (const float*)d_in[6];
    const float* W_attn = (const float*)d_in[7];
    const float* b_attn = (const float*)d_in[8];
    const float* W_val  = (const float*)d_in[9];
    const float* b_val  = (const float*)d_in[10];
    const float* W_out  = (const float*)d_in[11];
    const float* b_out  = (const float*)d_in[12];

    float* NEWQ = (float*)d_out;
    float* NEWV = NEWQ + NEWQ_SIZE_;

    float *p_offatt, *p_samp, *p_bcat;
    uint32_t *p_wb;
    cudaGetSymbolAddress((void**)&p_offatt, g_offatt);
    cudaGetSymbolAddress((void**)&p_samp,   g_samp);
    cudaGetSymbolAddress((void**)&p_bcat,   g_bcat);
    cudaGetSymbolAddress((void**)&p_wb,     g_wb);

    cudaFuncSetAttribute(hmma_gemm, cudaFuncAttributeMaxDynamicSharedMemorySize, VP_SMEM);

    // 1) prep K-permuted weight images + bias concat
    prep_images<<<5, 256>>>(W_val, W_off, W_attn, W_out);
    concat_bias<<<1, NCAT_>>>(b_off, b_attn);

    // 2) value projection -> new_value (persistent: 4 CTAs/SM x 148 SMs)
    {
        int mtiles = MVAL_ / CTM;               // 13770
        hmma_gemm<<<dim3(592, 1), 128, VP_SMEM>>>(
            value, p_wb, b_val, NEWV, MVAL_, 128, mtiles);
    }

    // 3) offsets + attn logits (3 weight chunks: indices 1..3)
    {
        int mtiles = (NROWS_ + CTM - 1) / CTM;  // 517
        hmma_gemm<<<dim3(mtiles, 3), 128, VP_SMEM>>>(
            query, p_wb + 8192, p_bcat, p_offatt, NROWS_, NCAT_, mtiles);
    }

    // 4) bilinear gather + fused softmax (8 warps/block)
    gather_kernel<<<NROWS_ * NH_ / 8, 256>>>(NEWV, refp);

    // 5) output projection -> new_query (chunk 4)
    {
        int mtiles = (NROWS_ + CTM - 1) / CTM;
        hmma_gemm<<<dim3(mtiles, 1), 128, VP_SMEM>>>(
            p_samp, p_wb + 4 * 8192, b_out, NEWQ, NROWS_, 128, mtiles);
    }
}